// round 6
// baseline (speedup 1.0000x reference)
#include <cuda_runtime.h>

#define NXc 64
#define NYc 64
#define NSPOTS 64
#define Pc 6
#define TPB 256          // 8 warps; warp w exclusively owns image rows [8w, 8w+8)

__global__ __launch_bounds__(TPB) void spot_render_kernel(
    const float* __restrict__ z, float* __restrict__ out)
{
    __shared__ float img[NXc * NYc];     // 16 KB, rotate-6 swizzled rows
    __shared__ float slx[NSPOTS * Pc];   // I0 * lam_x * valid
    __shared__ float sly[NSPOTS * Pc];   // lam_y * valid
    __shared__ int   spxy[NSPOTS];       // r0 | c0<<8  (r0=255 sentinel if invalid)
    __shared__ float sx0p[NSPOTS];
    __shared__ float sy0p[NSPOTS];
    __shared__ float sval[NSPOTS];
    __shared__ unsigned char slist[8][NSPOTS];

    const int b       = blockIdx.x;
    const int tid     = threadIdx.x;
    const int lane    = tid & 31;
    const int w       = tid >> 5;
    const int band_lo = w << 3;

    const float inv_alpha = 1.0f / (1.41421356237f * 0.92f);

    // ---- prologue: zero image (float4), per-spot meta ----
    {
        float4* im4 = reinterpret_cast<float4*>(img);
        #pragma unroll
        for (int i = tid; i < (NXc * NYc) / 4; i += TPB)
            im4[i] = make_float4(0.f, 0.f, 0.f, 0.f);
    }
    if (tid < NSPOTS) {
        const int s = tid;
        const float* zrow = z + (size_t)b * (2 * NSPOTS);
        const float x0 = __ldg(zrow + s);
        const float y0 = __ldg(zrow + NSPOTS + s);
        const int px = __float2int_rn(x0) - 3;          // round-half-even == jnp.round
        const int py = __float2int_rn(y0) - 3;
        const bool valid = (px >= 0) & (px < NXc - Pc) & (py >= 0) & (py < NYc - Pc);
        spxy[s] = (valid ? px : 255) | ((valid ? py : 0) << 8);   // 255 -> in no band
        sx0p[s] = x0 - (float)px;
        sy0p[s] = y0 - (float)py;
        sval[s] = valid ? 1.0f : 0.0f;
    }
    __syncthreads();

    // ---- build this warp's overlapping-spot list (ascending s -> deterministic) ----
    int cnt;
    {
        const int r0a = spxy[lane] & 255;
        const bool ova = (r0a + Pc > band_lo) && (r0a < band_lo + 8);
        const unsigned m0 = __ballot_sync(0xFFFFFFFFu, ova);
        const int r0b = spxy[lane + 32] & 255;
        const bool ovb = (r0b + Pc > band_lo) && (r0b < band_lo + 8);
        const unsigned m1 = __ballot_sync(0xFFFFFFFFu, ovb);
        const unsigned below = (1u << lane) - 1u;
        if (ova) slist[w][__popc(m0 & below)] = (unsigned char)lane;
        const int base = __popc(m0);
        if (ovb) slist[w][base + __popc(m1 & below)] = (unsigned char)(32 + lane);
        cnt = base + __popc(m1);
    }

    // ---- phase B: 768 lambda values ----
    #pragma unroll
    for (int k = 0; k < 3; k++) {
        const int i  = k * TPB + tid;
        const int s  = i & 63;
        const int jj = i >> 6;
        const bool isx = (jj < Pc);
        const float t  = (float)(isx ? jj : jj - Pc);
        const float t0 = isx ? sx0p[s] : sy0p[s];
        float lam = 0.5f * (erff((t + 0.5f - t0) * inv_alpha) -
                            erff((t - 0.5f - t0) * inv_alpha));
        lam *= sval[s];
        if (isx) slx[s * Pc + jj]        = lam * 1000.0f;   // fold I0
        else     sly[s * Pc + (jj - Pc)] = lam;
    }
    __syncthreads();

    // ---- phase C: band-owned RMW scatter (NO atomics) ----
    // clipped pixel q = 6*ixc + iy ; swizzled col = (c0 + 6*rs + q) & 63  -> banks
    // (B0+q) mod 32 distinct across the 32-lane pass: conflict-free LDS/STS.
    const int q1   = lane;
    const int ixc1 = (q1 * 171) >> 10;       // q/6 for q <= 35
    const int iy1  = q1 - ixc1 * Pc;
    const int iy2  = lane + 2;               // pass2: q = 32+lane -> ixc=5, iy=lane+2
    for (int k = 0; k < cnt; k++) {
        __syncwarp();                        // order prev iter's STS before this LDS
        const int s    = slist[w][k];        // warp-uniform broadcast
        const int meta = spxy[s];
        const int r0   = meta & 255;
        const int c0   = meta >> 8;
        const int rs   = max(r0, band_lo);
        const int re   = min(r0 + Pc, band_lo + 8);
        const int n6   = Pc * (re - rs);     // clipped pixel count (6..36)
        const int ix0  = rs - r0;
        const int B0   = c0 + 6 * rs;
        const float* lxp = &slx[s * Pc + ix0];
        const float* lyp = &sly[s * Pc];
        if (q1 < n6) {
            const int addr = ((rs + ixc1) << 6) + ((B0 + q1) & 63);
            img[addr] += lxp[ixc1] * lyp[iy1];
        }
        if (32 + lane < n6) {                // only when all 6 rows in band
            const int addr = ((rs + 5) << 6) + ((B0 + 32 + lane) & 63);
            img[addr] += lxp[5] * lyp[iy2];
        }
    }
    __syncthreads();

    // ---- phase D: un-swizzle + coalesced float2 writeback ----
    float2* o2 = reinterpret_cast<float2*>(out + (size_t)b * (NXc * NYc));
    const float2* im2 = reinterpret_cast<const float2*>(img);
    #pragma unroll
    for (int k = 0; k < 8; k++) {
        const int i  = k * TPB + tid;
        const int r  = i >> 5;               // warp-uniform
        const int cg = i & 31;
        o2[i] = im2[(r << 5) + ((cg + 3 * r) & 31)];
    }
}

extern "C" void kernel_launch(void* const* d_in, const int* in_sizes, int n_in,
                              void* d_out, int out_size)
{
    const float* z = (const float*)d_in[0];
    float* out = (float*)d_out;
    const int B = in_sizes[0] / (2 * NSPOTS);   // 8192
    spot_render_kernel<<<B, TPB>>>(z, out);
}

// round 7
// speedup vs baseline: 1.5921x; 1.5921x over previous
#include <cuda_runtime.h>

#define NXc 64
#define NYc 64
#define NSPOTS 64
#define Pc 6
#define TPB 256

__global__ __launch_bounds__(TPB) void spot_render_kernel(
    const float* __restrict__ z, float* __restrict__ out)
{
    __shared__ float img[NXc * NYc];     // 16 KB, rotate-6 swizzled rows
    __shared__ float slx[NSPOTS * Pc];   // 500 * dx * valid
    __shared__ float sly[NSPOTS * Pc];   // 0.5 * dy * valid
    __shared__ int   spxy[NSPOTS];       // clamped px | py<<8
    __shared__ float sx0p[NSPOTS];
    __shared__ float sy0p[NSPOTS];
    __shared__ float sval[NSPOTS];

    const int b    = blockIdx.x;
    const int tid  = threadIdx.x;
    const int lane = tid & 31;
    const int w    = tid >> 5;

    const float inv_alpha = 1.0f / (1.41421356237f * 0.92f);

    // ---- meta: one thread per spot ----
    if (tid < NSPOTS) {
        const int s = tid;
        const float* zrow = z + (size_t)b * (2 * NSPOTS);
        const float x0 = __ldg(zrow + s);
        const float y0 = __ldg(zrow + NSPOTS + s);
        const int px = __float2int_rn(x0) - 3;          // round-half-even == jnp.round
        const int py = __float2int_rn(y0) - 3;
        const bool valid = (px >= 0) & (px < NXc - Pc) & (py >= 0) & (py < NYc - Pc);
        spxy[s] = (valid ? px : 0) | ((valid ? py : 0) << 8);
        sx0p[s] = x0 - (float)px;
        sy0p[s] = y0 - (float)py;
        sval[s] = valid ? 1.0f : 0.0f;
    }
    __syncthreads();

    // ---- phase B (warps 0-3): 7 shared erfs per spot-dim -> 6 lambdas ----
    //      phase Z (warps 4-7): zero the 16 KB image concurrently
    if (tid < 128) {
        const int s = tid & 63;
        const int d = tid >> 6;                          // 0 = x, 1 = y
        const float t0 = d ? sy0p[s] : sx0p[s];
        const float scale = (d ? 0.5f : 500.0f) * sval[s];
        float e[7];
        #pragma unroll
        for (int j = 0; j < 7; j++)
            e[j] = erff(((float)j - 0.5f - t0) * inv_alpha);
        float* dst = (d ? sly : slx) + s * Pc;
        #pragma unroll
        for (int j = 0; j < 6; j++)
            dst[j] = (e[j + 1] - e[j]) * scale;
    } else {
        float4* im4 = reinterpret_cast<float4*>(img);
        const int i = tid - 128;
        #pragma unroll
        for (int k = 0; k < 8; k++)
            im4[k * 128 + i] = make_float4(0.f, 0.f, 0.f, 0.f);
    }
    __syncthreads();

    // ---- phase C: warp-per-8-spots scatter, conflict-free rotate-6 atomics ----
    // pixel p = 6*ix + iy; addr = (r0+ix)*64 + ((c0 + 6*r0 + p) & 63)
    // bank = (K + p) mod 32 with p distinct per lane -> zero conflicts
    const int p  = lane;
    const int ix = (p * 171) >> 10;          // p/6 for p <= 35
    const int iy = p - ix * Pc;
    #pragma unroll
    for (int k = 0; k < 8; k++) {
        const int s    = w * 8 + k;
        const int meta = spxy[s];            // broadcast
        const int r0   = meta & 255;
        const int c0   = meta >> 8;
        const int K    = (c0 + 6 * r0) & 63;
        const float v  = slx[s * Pc + ix] * sly[s * Pc + iy];
        atomicAdd(&img[((r0 + ix) << 6) + ((K + p) & 63)], v);
    }
    // batched residuals: pixels 32..35 (ix=5, iy=2..5) of all 8 spots in ONE atomic
    {
        const int s2   = w * 8 + (lane >> 2);
        const int p2   = 32 + (lane & 3);
        const int meta = spxy[s2];
        const int r0   = meta & 255;
        const int c0   = meta >> 8;
        const int K    = (c0 + 6 * r0) & 63;
        const float v  = slx[s2 * Pc + 5] * sly[s2 * Pc + (p2 - 30)];
        atomicAdd(&img[((r0 + 5) << 6) + ((K + p2) & 63)], v);
    }
    __syncthreads();

    // ---- phase D: un-swizzle + coalesced float2 writeback ----
    float2* o2 = reinterpret_cast<float2*>(out + (size_t)b * (NXc * NYc));
    const float2* im2 = reinterpret_cast<const float2*>(img);
    #pragma unroll
    for (int k = 0; k < 8; k++) {
        const int i  = k * TPB + tid;
        const int r  = i >> 5;               // warp-uniform
        const int cg = i & 31;
        o2[i] = im2[(r << 5) + ((cg + 3 * r) & 31)];
    }
}

extern "C" void kernel_launch(void* const* d_in, const int* in_sizes, int n_in,
                              void* d_out, int out_size)
{
    const float* z = (const float*)d_in[0];
    float* out = (float*)d_out;
    const int B = in_sizes[0] / (2 * NSPOTS);   // 8192
    spot_render_kernel<<<B, TPB>>>(z, out);
}